// round 16
// baseline (speedup 1.0000x reference)
#include <cuda_runtime.h>
#include <cuda_bf16.h>
#include <cstdint>

// ===========================================================================
// Problem constants
// ===========================================================================
#define B_SZ 32768
#define D_SZ 256
#define K_SZ 1024

#define NTHREADS 512       // 16 warps (proven config)
#define BK 32              // d-chunk per B pipeline stage (triple-buffered)
#define FB_CTAS 256        // fallback kernel grid

// --- SMEM layout (bytes) for K3 ---
#define BT_STRIDE 80
#define BT_SZ     10240          // 128*80
#define BUFB      20480          // 2 limbs
#define OFF_B     0              // 3 bufs -> 61440
#define AT_STRIDE 528
#define A_LIMB    67584          // 128*528
#define OFF_A     61440          // 2 limbs -> ends 196608
#define OFF_INVN  196608         // 256 floats -> 197632
#define SMEM_K3   197632
// merge arrays overlay the B region (only used after all MMA reads + sync)
#define OFF_CS1   0              // float [128][16] -> 8192
#define OFF_CI1   8192           // int   [128][16] -> 16384
#define OFF_CS2   16384          // float [128][16] -> 24576

// ===========================================================================
// Device scratch (allocation-free rule: __device__ globals)
// ===========================================================================
__device__ float g_inv_norms[K_SZ];
__device__ __align__(16) __nv_bfloat16 g_Chi[K_SZ * D_SZ];
__device__ __align__(16) __nv_bfloat16 g_Clo[K_SZ * D_SZ];
// per (quarter, row) top-2 approx results
__device__ float g_ts1[4 * B_SZ];
__device__ int   g_ti1[4 * B_SZ];
__device__ float g_ts2[4 * B_SZ];
// fallback compaction
__device__ int g_fb_count;
__device__ int g_fb_rows[B_SZ];

// ===========================================================================
// PTX helpers (plain sm_103-safe: mma.sync / ldmatrix / cp.async only)
// ===========================================================================
__device__ __forceinline__ uint32_t smem_u32(const void* p) {
    uint32_t a;
    asm("{ .reg .u64 t; cvta.to.shared.u64 t, %1; cvt.u32.u64 %0, t; }" : "=r"(a) : "l"(p));
    return a;
}
__device__ __forceinline__ void ldsm_x4(uint32_t r[4], uint32_t addr) {
    asm volatile("ldmatrix.sync.aligned.m8n8.x4.shared.b16 {%0,%1,%2,%3}, [%4];"
                 : "=r"(r[0]), "=r"(r[1]), "=r"(r[2]), "=r"(r[3]) : "r"(addr));
}
__device__ __forceinline__ void mma_bf16(float d[4], const uint32_t a[4], const uint32_t* b) {
    asm volatile(
        "mma.sync.aligned.m16n8k16.row.col.f32.bf16.bf16.f32 "
        "{%0,%1,%2,%3}, {%4,%5,%6,%7}, {%8,%9}, {%0,%1,%2,%3};"
        : "+f"(d[0]), "+f"(d[1]), "+f"(d[2]), "+f"(d[3])
        : "r"(a[0]), "r"(a[1]), "r"(a[2]), "r"(a[3]), "r"(b[0]), "r"(b[1]));
}
#define CP_ASYNC16(dst, src) \
    asm volatile("cp.async.cg.shared.global [%0], [%1], 16;" :: "r"(dst), "l"(src) : "memory")
#define CP_COMMIT() asm volatile("cp.async.commit_group;" ::: "memory")
#define CP_WAIT(N)  asm volatile("cp.async.wait_group %0;" :: "n"(N) : "memory")

__device__ __forceinline__ float warp_allsum(float v) {
#pragma unroll
    for (int o = 16; o > 0; o >>= 1) v += __shfl_xor_sync(0xffffffffu, v, o);
    return v;
}

// ===========================================================================
// K1 (prep): C 2-limb split + inv_norms + fb counter reset.
// ===========================================================================
__global__ void vq_prep_kernel(const float* __restrict__ C) {
    const int k = blockIdx.x;
    const int t = threadIdx.x;           // 0..63
    if (k == 0 && t == 0) g_fb_count = 0;

    float4 v = __ldg(reinterpret_cast<const float4*>(C + (size_t)k * D_SZ) + t);
    float ss = v.x * v.x + v.y * v.y + v.z * v.z + v.w * v.w;

    union U4 { __nv_bfloat16 h[4]; uint2 u; } uh, ul;
    float vv[4] = {v.x, v.y, v.z, v.w};
#pragma unroll
    for (int j = 0; j < 4; j++) {
        __nv_bfloat16 bh = __float2bfloat16_rn(vv[j]);
        float r = vv[j] - __bfloat162float(bh);
        uh.h[j] = bh;
        ul.h[j] = __float2bfloat16_rn(r);
    }
    *reinterpret_cast<uint2*>(g_Chi + (size_t)k * D_SZ + t * 4) = uh.u;
    *reinterpret_cast<uint2*>(g_Clo + (size_t)k * D_SZ + t * 4) = ul.u;

    __shared__ float sred[2];
    ss = warp_allsum(ss);
    if ((t & 31) == 0) sred[t >> 5] = ss;
    __syncthreads();
    if (t == 0) g_inv_norms[k] = 1.0f / (sred[0] + sred[1]);
}

// ===========================================================================
// K3: 3-term split-bf16 mma.sync GEMM + per-row approx top-2 (per quarter)
// ===========================================================================
__global__ __launch_bounds__(NTHREADS, 1) void vq_gemm_kernel(const float* __restrict__ E) {
    extern __shared__ char smem[];
    const uint32_t sb = smem_u32(smem);
    const int tid = threadIdx.x;
    const int lane = tid & 31;
    const int wid = tid >> 5;      // 0..15
    const int wm = wid & 3;        // M group: rows wm*32..+32
    const int wn = wid >> 2;       // N group: codes wn*32..+32 (within 128-pass)
    const int rb = blockIdx.x >> 2;
    const int q  = blockIdx.x & 3;
    const int rowA0 = rb * 128;

    float* s_invn = reinterpret_cast<float*>(smem + OFF_INVN);
    if (tid < 256) s_invn[tid] = g_inv_norms[q * 256 + tid];

    // B chunk loader: 128 codes x 32 d x 2 limbs = 16 KB -> 2 x 16B / thread
    auto loadB = [&](int buf, int kk, int codeB0) {
#pragma unroll
        for (int j = 0; j < 2; j++) {
            int id = tid + NTHREADS * j;       // 0..1023
            int limb = id >> 9;
            int w = id & 511;
            int r = w >> 2;                    // 0..127
            int c = w & 3;                     // 16B column
            const __nv_bfloat16* base = limb ? g_Clo : g_Chi;
            CP_ASYNC16(sb + OFF_B + buf * BUFB + limb * BT_SZ + r * BT_STRIDE + c * 16,
                       base + (size_t)(codeB0 + r) * D_SZ + kk + c * 8);
        }
        CP_COMMIT();
    };

    // issue first B chunks of pass 0 before the A prologue (overlap)
    loadB(0, 0, q * 256);
    loadB(1, BK, q * 256);

    // --- A prologue: LDG fp32 E rows, split to bf16 limbs, STS (132 KB) ---
    {
        const float4* E4 = reinterpret_cast<const float4*>(E);
#pragma unroll
        for (int j = 0; j < 16; j++) {
            int id = tid + NTHREADS * j;       // 0..8191
            int r = id >> 6;                   // 0..127
            int c4 = id & 63;                  // float4 column
            float4 v = __ldg(E4 + (size_t)(rowA0 + r) * 64 + c4);
            union U4 { __nv_bfloat16 h[4]; uint2 u; } uh, ul;
            float vv[4] = {v.x, v.y, v.z, v.w};
#pragma unroll
            for (int e = 0; e < 4; e++) {
                __nv_bfloat16 bh = __float2bfloat16_rn(vv[e]);
                float rr = vv[e] - __bfloat162float(bh);
                uh.h[e] = bh;
                ul.h[e] = __float2bfloat16_rn(rr);
            }
            *reinterpret_cast<uint2*>(smem + OFF_A + r * AT_STRIDE + c4 * 8) = uh.u;
            *reinterpret_cast<uint2*>(smem + OFF_A + A_LIMB + r * AT_STRIDE + c4 * 8) = ul.u;
        }
    }

    // per-thread top-2 state for 4 owned rows (mt*2 + half)
    float st_s1[4], st_s2[4];
    int   st_i1[4];
#pragma unroll
    for (int i = 0; i < 4; i++) { st_s1[i] = -1.f; st_s2[i] = -1.f; st_i1[i] = 0; }

    const int mi = lane >> 3;
    const int arow_off = ((mi & 1) * 8 + (lane & 7)) * AT_STRIDE;
    const int brow_off = ((mi >> 1) * 8 + (lane & 7)) * BT_STRIDE;

    for (int p = 0; p < 2; p++) {
        const int codeB0 = q * 256 + p * 128;
        float d[2][4][4];
#pragma unroll
        for (int mt = 0; mt < 2; mt++)
#pragma unroll
            for (int nt = 0; nt < 4; nt++)
#pragma unroll
                for (int e = 0; e < 4; e++) d[mt][nt][e] = 0.f;

        if (p == 1) { loadB(0, 0, codeB0); loadB(1, BK, codeB0); }
        for (int kc = 0; kc < 8; kc++) {
            const int buf = kc % 3;
            if (kc < 7) { CP_WAIT(1); } else { CP_WAIT(0); }
            __syncthreads();     // also orders the A-prologue STS on kc==0
            if (kc < 6) loadB((kc + 2) % 3, (kc + 2) * BK, codeB0);

#pragma unroll
            for (int ks2 = 0; ks2 < 2; ks2++) {
                const int d0 = kc * BK + ks2 * 16;
                const int ksl = ks2 * 16;
                uint32_t afr[2][2][4];
#pragma unroll
                for (int lb = 0; lb < 2; lb++)
#pragma unroll
                    for (int mt = 0; mt < 2; mt++) {
                        uint32_t ad = sb + OFF_A + lb * A_LIMB
                                    + (wm * 32 + mt * 16) * AT_STRIDE + arow_off
                                    + (d0 + (mi >> 1) * 8) * 2;
                        ldsm_x4(afr[lb][mt], ad);
                    }
#pragma unroll
                for (int np = 0; np < 2; np++) {
                    uint32_t bh[4], bl[4];
                    uint32_t bd0 = sb + OFF_B + buf * BUFB
                                 + (wn * 32 + np * 16) * BT_STRIDE + brow_off
                                 + (ksl + (mi & 1) * 8) * 2;
                    ldsm_x4(bh, bd0);
                    ldsm_x4(bl, bd0 + BT_SZ);
#pragma unroll
                    for (int jj = 0; jj < 2; jj++) {
                        int nt = np * 2 + jj;
#pragma unroll
                        for (int mt = 0; mt < 2; mt++) {
                            mma_bf16(d[mt][nt], afr[0][mt], bh + jj * 2);  // hi*hi
                            mma_bf16(d[mt][nt], afr[0][mt], bl + jj * 2);  // hi*lo
                            mma_bf16(d[mt][nt], afr[1][mt], bh + jj * 2);  // lo*hi
                        }
                    }
                }
            }
        }
        __syncthreads();

        // epilogue: fold 128 codes into per-row top-2
#pragma unroll
        for (int mt = 0; mt < 2; mt++)
#pragma unroll
            for (int nt = 0; nt < 4; nt++) {
                int cb = wn * 32 + nt * 8 + (lane & 3) * 2;
                int cl = p * 128 + cb;
                float in0 = s_invn[cl], in1 = s_invn[cl + 1];
                int gc = q * 256 + cl;
#pragma unroll
                for (int half = 0; half < 2; half++) {
                    int si = mt * 2 + half;
                    float e0 = d[mt][nt][half * 2 + 0];
                    float e1 = d[mt][nt][half * 2 + 1];
                    float sc0 = e0 * e0 * in0;
                    if (sc0 > st_s1[si]) { st_s2[si] = st_s1[si]; st_s1[si] = sc0; st_i1[si] = gc; }
                    else if (sc0 > st_s2[si]) st_s2[si] = sc0;
                    float sc1 = e1 * e1 * in1;
                    if (sc1 > st_s1[si]) { st_s2[si] = st_s1[si]; st_s1[si] = sc1; st_i1[si] = gc + 1; }
                    else if (sc1 > st_s2[si]) st_s2[si] = sc1;
                }
            }
    }

    // overlay merge arrays on the B region
    float* c_s1 = reinterpret_cast<float*>(smem + OFF_CS1);
    int*   c_i1 = reinterpret_cast<int*>(smem + OFF_CI1);
    float* c_s2 = reinterpret_cast<float*>(smem + OFF_CS2);

#pragma unroll
    for (int mt = 0; mt < 2; mt++)
#pragma unroll
        for (int half = 0; half < 2; half++) {
            int r = wm * 32 + mt * 16 + half * 8 + (lane >> 2);
            int slot = wn * 4 + (lane & 3);
            int si = mt * 2 + half;
            c_s1[r * 16 + slot] = st_s1[si];
            c_i1[r * 16 + slot] = st_i1[si];
            c_s2[r * 16 + slot] = st_s2[si];
        }
    __syncthreads();
    if (tid < 128) {
        float S1 = -1.f, S2 = -1.f; int I1 = 0;
#pragma unroll
        for (int s = 0; s < 16; s++) {
            float a1 = c_s1[tid * 16 + s];
            int   ai = c_i1[tid * 16 + s];
            float a2 = c_s2[tid * 16 + s];
            if (a1 > S1) { S2 = (S1 > a2) ? S1 : a2; I1 = ai; S1 = a1; }
            else if (a1 > S2) S2 = a1;
        }
        int o = q * B_SZ + rowA0 + tid;
        g_ts1[o] = S1; g_ti1[o] = I1; g_ts2[o] = S2;
    }
}

// ===========================================================================
// K4: quarter-certify. thr = gS1 - eps.
//   - if any quarter's S2 >= thr: full-rescan fallback (rare)
//   - else: true winner is among quarter winners with qs1 >= thr (1..4);
//     exact-rescore those, pick argmax (min index on ties), write z/idx.
// One warp per row.
// ===========================================================================
__global__ __launch_bounds__(256) void vq_final_kernel(
    const float* __restrict__ E, const float* __restrict__ C,
    float* __restrict__ z_out, float* __restrict__ idx_out, int write_idx)
{
    int warp = threadIdx.x >> 5;
    int lane = threadIdx.x & 31;
    int row = blockIdx.x * 8 + warp;
    const float4* E4 = reinterpret_cast<const float4*>(E);
    const float4* C4 = reinterpret_cast<const float4*>(C);

    float4 ev0 = E4[(size_t)row * 64 + lane * 2];
    float4 ev1 = E4[(size_t)row * 64 + lane * 2 + 1];
    float en2 = warp_allsum(ev0.x * ev0.x + ev0.y * ev0.y + ev0.z * ev0.z + ev0.w * ev0.w +
                            ev1.x * ev1.x + ev1.y * ev1.y + ev1.z * ev1.z + ev1.w * ev1.w);

    float qs1[4], qs2[4]; int qi1[4];
#pragma unroll
    for (int qq = 0; qq < 4; qq++) {
        qs1[qq] = g_ts1[qq * B_SZ + row];
        qi1[qq] = g_ti1[qq * B_SZ + row];
        qs2[qq] = g_ts2[qq * B_SZ + row];
    }
    float gS1 = qs1[0];
#pragma unroll
    for (int qq = 1; qq < 4; qq++) if (qs1[qq] > gS1) gS1 = qs1[qq];

    const float eps = en2 * (1.0f / 8192.0f);   // 2^-13 * ||e||^2 (proven)
    const float thr = gS1 - eps;

    bool needfull = false;
#pragma unroll
    for (int qq = 0; qq < 4; qq++) needfull |= (qs2[qq] >= thr);

    if (needfull) {
        if (lane == 0) {
            int pos = atomicAdd(&g_fb_count, 1);
            g_fb_rows[pos] = row;
        }
        return;
    }

    // exact-rescore qualifying quarter winners (1..4 candidates)
    float bestsc = -1.f; int bestk = 0; float bestdot = 0.f;
#pragma unroll
    for (int qq = 0; qq < 4; qq++) {
        if (qs1[qq] >= thr) {
            int k = qi1[qq];
            float4 c0 = __ldg(&C4[(size_t)k * 64 + lane * 2]);
            float4 c1 = __ldg(&C4[(size_t)k * 64 + lane * 2 + 1]);
            float pp = ev0.x * c0.x + ev0.y * c0.y + ev0.z * c0.z + ev0.w * c0.w +
                       ev1.x * c1.x + ev1.y * c1.y + ev1.z * c1.z + ev1.w * c1.w;
            float dot = warp_allsum(pp);
            float sc = dot * dot * g_inv_norms[k];
            if (sc > bestsc || (sc == bestsc && k < bestk)) {
                bestsc = sc; bestk = k; bestdot = dot;
            }
        }
    }

    float alpha = bestdot * g_inv_norms[bestk];
    float4 cv0 = __ldg(&C4[(size_t)bestk * 64 + lane * 2]);
    float4 cv1 = __ldg(&C4[(size_t)bestk * 64 + lane * 2 + 1]);
    float4* Z4 = reinterpret_cast<float4*>(z_out);
    Z4[(size_t)row * 64 + lane * 2] =
        make_float4(alpha * cv0.x, alpha * cv0.y, alpha * cv0.z, alpha * cv0.w);
    Z4[(size_t)row * 64 + lane * 2 + 1] =
        make_float4(alpha * cv1.x, alpha * cv1.y, alpha * cv1.z, alpha * cv1.w);
    if (lane == 0 && write_idx) idx_out[row] = (float)bestk;
}

// ===========================================================================
// K5: exact fp32 rescan for fallback rows. 8 rows per CTA (grid-stride).
// ===========================================================================
__global__ __launch_bounds__(256) void vq_fb_kernel(
    const float* __restrict__ E, const float* __restrict__ C,
    float* __restrict__ z_out, float* __restrict__ idx_out, int write_idx)
{
    __shared__ float se[8][256];
    __shared__ float ws[8][8];   // [row][warp]
    __shared__ int   wi[8][8];
    __shared__ int   s_rid[8];
    __shared__ int   s_kb[8];
    const int tid = threadIdx.x;
    const int warp = tid >> 5;
    const int lane = tid & 31;
    const float4* C4 = reinterpret_cast<const float4*>(C);

    const int nfb = g_fb_count;
    const int ngrp = (nfb + 7) >> 3;
    for (int g = blockIdx.x; g < ngrp; g += FB_CTAS) {
        const int r0 = g * 8;
        const int cnt = (nfb - r0 < 8) ? (nfb - r0) : 8;
        if (tid < 8) s_rid[tid] = (tid < cnt) ? g_fb_rows[r0 + tid] : -1;
        __syncthreads();
#pragma unroll
        for (int rr = 0; rr < 8; rr++)
            se[rr][tid] = (s_rid[rr] >= 0) ? E[(size_t)s_rid[rr] * D_SZ + tid] : 0.f;
        __syncthreads();

        float4 ea[8], eb[8];
#pragma unroll
        for (int r = 0; r < 8; r++) {
            ea[r] = *reinterpret_cast<const float4*>(&se[r][lane * 8]);
            eb[r] = *reinterpret_cast<const float4*>(&se[r][lane * 8 + 4]);
        }

        float best[8]; int bi[8];
#pragma unroll
        for (int r = 0; r < 8; r++) { best[r] = -1.f; bi[r] = 0; }

        const int k0 = warp * 128;
        for (int kk = 0; kk < 128; kk++) {
            const int k = k0 + kk;
            float4 c0 = __ldg(&C4[(size_t)k * 64 + lane * 2]);
            float4 c1 = __ldg(&C4[(size_t)k * 64 + lane * 2 + 1]);
            float pp[8];
#pragma unroll
            for (int r = 0; r < 8; r++)
                pp[r] = ea[r].x * c0.x + ea[r].y * c0.y + ea[r].z * c0.z + ea[r].w * c0.w +
                        eb[r].x * c1.x + eb[r].y * c1.y + eb[r].z * c1.z + eb[r].w * c1.w;
#pragma unroll
            for (int o = 16; o > 0; o >>= 1)
#pragma unroll
                for (int r = 0; r < 8; r++)
                    pp[r] += __shfl_xor_sync(0xffffffffu, pp[r], o);
            const float invn = g_inv_norms[k];
#pragma unroll
            for (int r = 0; r < 8; r++) {
                float sc = pp[r] * pp[r] * invn;
                if (sc > best[r]) { best[r] = sc; bi[r] = k; }  // ascending k
            }
        }
        if (lane == 0) {
#pragma unroll
            for (int r = 0; r < 8; r++) { ws[r][warp] = best[r]; wi[r][warp] = bi[r]; }
        }
        __syncthreads();
        if (tid < 8) {
            float bb = -1.f; int bk = 0;
#pragma unroll
            for (int w = 0; w < 8; w++)
                if (ws[tid][w] > bb) { bb = ws[tid][w]; bk = wi[tid][w]; }
            s_kb[tid] = bk;
        }
        __syncthreads();

        const int row = s_rid[warp];
        if (row >= 0) {
            const int kb = s_kb[warp];
            float4 c0 = __ldg(&C4[(size_t)kb * 64 + lane * 2]);
            float4 c1 = __ldg(&C4[(size_t)kb * 64 + lane * 2 + 1]);
            float pp = ea[warp].x * c0.x + ea[warp].y * c0.y + ea[warp].z * c0.z + ea[warp].w * c0.w +
                       eb[warp].x * c1.x + eb[warp].y * c1.y + eb[warp].z * c1.z + eb[warp].w * c1.w;
            float dot = warp_allsum(pp);
            float alpha = dot * g_inv_norms[kb];
            float4* Z4 = reinterpret_cast<float4*>(z_out);
            Z4[(size_t)row * 64 + lane * 2] =
                make_float4(alpha * c0.x, alpha * c0.y, alpha * c0.z, alpha * c0.w);
            Z4[(size_t)row * 64 + lane * 2 + 1] =
                make_float4(alpha * c1.x, alpha * c1.y, alpha * c1.z, alpha * c1.w);
            if (lane == 0 && write_idx) idx_out[row] = (float)kb;
        }
        __syncthreads();
    }
}

// ===========================================================================
extern "C" void kernel_launch(void* const* d_in, const int* in_sizes, int n_in,
                              void* d_out, int out_size) {
    const float* E = (const float*)d_in[0];
    const float* C = (const float*)d_in[1];
    float* z = (float*)d_out;
    float* idx = z + (size_t)B_SZ * D_SZ;
    int write_idx = (out_size >= B_SZ * D_SZ + B_SZ) ? 1 : 0;

    cudaFuncSetAttribute(vq_gemm_kernel,
                         cudaFuncAttributeMaxDynamicSharedMemorySize, SMEM_K3);

    vq_prep_kernel<<<K_SZ, 64>>>(C);
    vq_gemm_kernel<<<(B_SZ / 128) * 4, NTHREADS, SMEM_K3>>>(E);
    vq_final_kernel<<<B_SZ / 8, 256>>>(E, C, z, idx, write_idx);
    vq_fb_kernel<<<FB_CTAS, 256>>>(E, C, z, idx, write_idx);
}

// round 17
// speedup vs baseline: 1.0543x; 1.0543x over previous
#include <cuda_runtime.h>
#include <cuda_bf16.h>
#include <cstdint>

// ===========================================================================
// Problem constants
// ===========================================================================
#define B_SZ 32768
#define D_SZ 256
#define K_SZ 1024

#define NTHREADS 512       // 16 warps (proven config)
#define BK 32              // d-chunk per B pipeline stage (triple-buffered)
#define FB_CTAS 128        // fallback kernel grid (512 threads each)

// --- SMEM layout (bytes) for K3 ---
#define BT_STRIDE 80
#define BT_SZ     10240          // 128*80
#define BUFB      20480          // 2 limbs
#define OFF_B     0              // 3 bufs -> 61440
#define AT_STRIDE 528
#define A_LIMB    67584          // 128*528
#define OFF_A     61440          // 2 limbs -> ends 196608
#define OFF_INVN  196608         // 256 floats -> 197632
#define SMEM_K3   197632
// merge arrays overlay the B region (only used after all MMA reads + sync)
#define OFF_CS1   0              // float [128][16] -> 8192
#define OFF_CI1   8192           // int   [128][16] -> 16384
#define OFF_CS2   16384          // float [128][16] -> 24576

// ===========================================================================
// Device scratch (allocation-free rule: __device__ globals)
// ===========================================================================
__device__ float g_inv_norms[K_SZ];
__device__ __align__(16) __nv_bfloat16 g_Chi[K_SZ * D_SZ];
__device__ __align__(16) __nv_bfloat16 g_Clo[K_SZ * D_SZ];
// per (quarter, row) top-2 approx results
__device__ float g_ts1[4 * B_SZ];
__device__ int   g_ti1[4 * B_SZ];
__device__ float g_ts2[4 * B_SZ];
// fallback compaction
__device__ int g_fb_count;
__device__ int g_fb_rows[B_SZ];

// ===========================================================================
// PTX helpers (plain sm_103-safe: mma.sync / ldmatrix / cp.async only)
// ===========================================================================
__device__ __forceinline__ uint32_t smem_u32(const void* p) {
    uint32_t a;
    asm("{ .reg .u64 t; cvta.to.shared.u64 t, %1; cvt.u32.u64 %0, t; }" : "=r"(a) : "l"(p));
    return a;
}
__device__ __forceinline__ void ldsm_x4(uint32_t r[4], uint32_t addr) {
    asm volatile("ldmatrix.sync.aligned.m8n8.x4.shared.b16 {%0,%1,%2,%3}, [%4];"
                 : "=r"(r[0]), "=r"(r[1]), "=r"(r[2]), "=r"(r[3]) : "r"(addr));
}
__device__ __forceinline__ void mma_bf16(float d[4], const uint32_t a[4], const uint32_t* b) {
    asm volatile(
        "mma.sync.aligned.m16n8k16.row.col.f32.bf16.bf16.f32 "
        "{%0,%1,%2,%3}, {%4,%5,%6,%7}, {%8,%9}, {%0,%1,%2,%3};"
        : "+f"(d[0]), "+f"(d[1]), "+f"(d[2]), "+f"(d[3])
        : "r"(a[0]), "r"(a[1]), "r"(a[2]), "r"(a[3]), "r"(b[0]), "r"(b[1]));
}
#define CP_ASYNC16(dst, src) \
    asm volatile("cp.async.cg.shared.global [%0], [%1], 16;" :: "r"(dst), "l"(src) : "memory")
#define CP_COMMIT() asm volatile("cp.async.commit_group;" ::: "memory")
#define CP_WAIT(N)  asm volatile("cp.async.wait_group %0;" :: "n"(N) : "memory")

__device__ __forceinline__ float warp_allsum(float v) {
#pragma unroll
    for (int o = 16; o > 0; o >>= 1) v += __shfl_xor_sync(0xffffffffu, v, o);
    return v;
}

// ===========================================================================
// K1 (prep): C 2-limb split + inv_norms + fb counter reset.
// ===========================================================================
__global__ void vq_prep_kernel(const float* __restrict__ C) {
    const int k = blockIdx.x;
    const int t = threadIdx.x;           // 0..63
    if (k == 0 && t == 0) g_fb_count = 0;

    float4 v = __ldg(reinterpret_cast<const float4*>(C + (size_t)k * D_SZ) + t);
    float ss = v.x * v.x + v.y * v.y + v.z * v.z + v.w * v.w;

    union U4 { __nv_bfloat16 h[4]; uint2 u; } uh, ul;
    float vv[4] = {v.x, v.y, v.z, v.w};
#pragma unroll
    for (int j = 0; j < 4; j++) {
        __nv_bfloat16 bh = __float2bfloat16_rn(vv[j]);
        float r = vv[j] - __bfloat162float(bh);
        uh.h[j] = bh;
        ul.h[j] = __float2bfloat16_rn(r);
    }
    *reinterpret_cast<uint2*>(g_Chi + (size_t)k * D_SZ + t * 4) = uh.u;
    *reinterpret_cast<uint2*>(g_Clo + (size_t)k * D_SZ + t * 4) = ul.u;

    __shared__ float sred[2];
    ss = warp_allsum(ss);
    if ((t & 31) == 0) sred[t >> 5] = ss;
    __syncthreads();
    if (t == 0) g_inv_norms[k] = 1.0f / (sred[0] + sred[1]);
}

// ===========================================================================
// K3: 3-term split-bf16 mma.sync GEMM + per-row approx top-2 (per quarter)
// ===========================================================================
__global__ __launch_bounds__(NTHREADS, 1) void vq_gemm_kernel(const float* __restrict__ E) {
    extern __shared__ char smem[];
    const uint32_t sb = smem_u32(smem);
    const int tid = threadIdx.x;
    const int lane = tid & 31;
    const int wid = tid >> 5;      // 0..15
    const int wm = wid & 3;        // M group: rows wm*32..+32
    const int wn = wid >> 2;       // N group: codes wn*32..+32 (within 128-pass)
    const int rb = blockIdx.x >> 2;
    const int q  = blockIdx.x & 3;
    const int rowA0 = rb * 128;

    float* s_invn = reinterpret_cast<float*>(smem + OFF_INVN);
    if (tid < 256) s_invn[tid] = g_inv_norms[q * 256 + tid];

    // B chunk loader: 128 codes x 32 d x 2 limbs = 16 KB -> 2 x 16B / thread
    auto loadB = [&](int buf, int kk, int codeB0) {
#pragma unroll
        for (int j = 0; j < 2; j++) {
            int id = tid + NTHREADS * j;       // 0..1023
            int limb = id >> 9;
            int w = id & 511;
            int r = w >> 2;                    // 0..127
            int c = w & 3;                     // 16B column
            const __nv_bfloat16* base = limb ? g_Clo : g_Chi;
            CP_ASYNC16(sb + OFF_B + buf * BUFB + limb * BT_SZ + r * BT_STRIDE + c * 16,
                       base + (size_t)(codeB0 + r) * D_SZ + kk + c * 8);
        }
        CP_COMMIT();
    };

    // issue first B chunks of pass 0 before the A prologue (overlap)
    loadB(0, 0, q * 256);
    loadB(1, BK, q * 256);

    // --- A prologue: LDG fp32 E rows, split to bf16 limbs, STS (132 KB) ---
    {
        const float4* E4 = reinterpret_cast<const float4*>(E);
#pragma unroll
        for (int j = 0; j < 16; j++) {
            int id = tid + NTHREADS * j;       // 0..8191
            int r = id >> 6;                   // 0..127
            int c4 = id & 63;                  // float4 column
            float4 v = __ldg(E4 + (size_t)(rowA0 + r) * 64 + c4);
            union U4 { __nv_bfloat16 h[4]; uint2 u; } uh, ul;
            float vv[4] = {v.x, v.y, v.z, v.w};
#pragma unroll
            for (int e = 0; e < 4; e++) {
                __nv_bfloat16 bh = __float2bfloat16_rn(vv[e]);
                float rr = vv[e] - __bfloat162float(bh);
                uh.h[e] = bh;
                ul.h[e] = __float2bfloat16_rn(rr);
            }
            *reinterpret_cast<uint2*>(smem + OFF_A + r * AT_STRIDE + c4 * 8) = uh.u;
            *reinterpret_cast<uint2*>(smem + OFF_A + A_LIMB + r * AT_STRIDE + c4 * 8) = ul.u;
        }
    }

    // per-thread top-2 state for 4 owned rows (mt*2 + half)
    float st_s1[4], st_s2[4];
    int   st_i1[4];
#pragma unroll
    for (int i = 0; i < 4; i++) { st_s1[i] = -1.f; st_s2[i] = -1.f; st_i1[i] = 0; }

    const int mi = lane >> 3;
    const int arow_off = ((mi & 1) * 8 + (lane & 7)) * AT_STRIDE;
    const int brow_off = ((mi >> 1) * 8 + (lane & 7)) * BT_STRIDE;

    for (int p = 0; p < 2; p++) {
        const int codeB0 = q * 256 + p * 128;
        float d[2][4][4];
#pragma unroll
        for (int mt = 0; mt < 2; mt++)
#pragma unroll
            for (int nt = 0; nt < 4; nt++)
#pragma unroll
                for (int e = 0; e < 4; e++) d[mt][nt][e] = 0.f;

        if (p == 1) { loadB(0, 0, codeB0); loadB(1, BK, codeB0); }
        for (int kc = 0; kc < 8; kc++) {
            const int buf = kc % 3;
            if (kc < 7) { CP_WAIT(1); } else { CP_WAIT(0); }
            __syncthreads();     // also orders the A-prologue STS on kc==0
            if (kc < 6) loadB((kc + 2) % 3, (kc + 2) * BK, codeB0);

#pragma unroll
            for (int ks2 = 0; ks2 < 2; ks2++) {
                const int d0 = kc * BK + ks2 * 16;
                const int ksl = ks2 * 16;
                uint32_t afr[2][2][4];
#pragma unroll
                for (int lb = 0; lb < 2; lb++)
#pragma unroll
                    for (int mt = 0; mt < 2; mt++) {
                        uint32_t ad = sb + OFF_A + lb * A_LIMB
                                    + (wm * 32 + mt * 16) * AT_STRIDE + arow_off
                                    + (d0 + (mi >> 1) * 8) * 2;
                        ldsm_x4(afr[lb][mt], ad);
                    }
#pragma unroll
                for (int np = 0; np < 2; np++) {
                    uint32_t bh[4], bl[4];
                    uint32_t bd0 = sb + OFF_B + buf * BUFB
                                 + (wn * 32 + np * 16) * BT_STRIDE + brow_off
                                 + (ksl + (mi & 1) * 8) * 2;
                    ldsm_x4(bh, bd0);
                    ldsm_x4(bl, bd0 + BT_SZ);
#pragma unroll
                    for (int jj = 0; jj < 2; jj++) {
                        int nt = np * 2 + jj;
#pragma unroll
                        for (int mt = 0; mt < 2; mt++) {
                            mma_bf16(d[mt][nt], afr[0][mt], bh + jj * 2);  // hi*hi
                            mma_bf16(d[mt][nt], afr[0][mt], bl + jj * 2);  // hi*lo
                            mma_bf16(d[mt][nt], afr[1][mt], bh + jj * 2);  // lo*hi
                        }
                    }
                }
            }
        }
        __syncthreads();

        // epilogue: fold 128 codes into per-row top-2
#pragma unroll
        for (int mt = 0; mt < 2; mt++)
#pragma unroll
            for (int nt = 0; nt < 4; nt++) {
                int cb = wn * 32 + nt * 8 + (lane & 3) * 2;
                int cl = p * 128 + cb;
                float in0 = s_invn[cl], in1 = s_invn[cl + 1];
                int gc = q * 256 + cl;
#pragma unroll
                for (int half = 0; half < 2; half++) {
                    int si = mt * 2 + half;
                    float e0 = d[mt][nt][half * 2 + 0];
                    float e1 = d[mt][nt][half * 2 + 1];
                    float sc0 = e0 * e0 * in0;
                    if (sc0 > st_s1[si]) { st_s2[si] = st_s1[si]; st_s1[si] = sc0; st_i1[si] = gc; }
                    else if (sc0 > st_s2[si]) st_s2[si] = sc0;
                    float sc1 = e1 * e1 * in1;
                    if (sc1 > st_s1[si]) { st_s2[si] = st_s1[si]; st_s1[si] = sc1; st_i1[si] = gc + 1; }
                    else if (sc1 > st_s2[si]) st_s2[si] = sc1;
                }
            }
    }

    // overlay merge arrays on the B region
    float* c_s1 = reinterpret_cast<float*>(smem + OFF_CS1);
    int*   c_i1 = reinterpret_cast<int*>(smem + OFF_CI1);
    float* c_s2 = reinterpret_cast<float*>(smem + OFF_CS2);

#pragma unroll
    for (int mt = 0; mt < 2; mt++)
#pragma unroll
        for (int half = 0; half < 2; half++) {
            int r = wm * 32 + mt * 16 + half * 8 + (lane >> 2);
            int slot = wn * 4 + (lane & 3);
            int si = mt * 2 + half;
            c_s1[r * 16 + slot] = st_s1[si];
            c_i1[r * 16 + slot] = st_i1[si];
            c_s2[r * 16 + slot] = st_s2[si];
        }
    __syncthreads();
    if (tid < 128) {
        float S1 = -1.f, S2 = -1.f; int I1 = 0;
#pragma unroll
        for (int s = 0; s < 16; s++) {
            float a1 = c_s1[tid * 16 + s];
            int   ai = c_i1[tid * 16 + s];
            float a2 = c_s2[tid * 16 + s];
            if (a1 > S1) { S2 = (S1 > a2) ? S1 : a2; I1 = ai; S1 = a1; }
            else if (a1 > S2) S2 = a1;
        }
        int o = q * B_SZ + rowA0 + tid;
        g_ts1[o] = S1; g_ti1[o] = I1; g_ts2[o] = S2;
    }
}

// ===========================================================================
// K4: quarter-certify. thr = gS1 - eps.
//   - if any quarter's S2 >= thr: full-rescan fallback (rare)
//   - else: exact-rescore qualifying quarter winners (1..4), write z/idx.
// One warp per row.
// ===========================================================================
__global__ __launch_bounds__(256) void vq_final_kernel(
    const float* __restrict__ E, const float* __restrict__ C,
    float* __restrict__ z_out, float* __restrict__ idx_out, int write_idx)
{
    int warp = threadIdx.x >> 5;
    int lane = threadIdx.x & 31;
    int row = blockIdx.x * 8 + warp;
    const float4* E4 = reinterpret_cast<const float4*>(E);
    const float4* C4 = reinterpret_cast<const float4*>(C);

    float4 ev0 = E4[(size_t)row * 64 + lane * 2];
    float4 ev1 = E4[(size_t)row * 64 + lane * 2 + 1];
    float en2 = warp_allsum(ev0.x * ev0.x + ev0.y * ev0.y + ev0.z * ev0.z + ev0.w * ev0.w +
                            ev1.x * ev1.x + ev1.y * ev1.y + ev1.z * ev1.z + ev1.w * ev1.w);

    float qs1[4], qs2[4]; int qi1[4];
#pragma unroll
    for (int qq = 0; qq < 4; qq++) {
        qs1[qq] = g_ts1[qq * B_SZ + row];
        qi1[qq] = g_ti1[qq * B_SZ + row];
        qs2[qq] = g_ts2[qq * B_SZ + row];
    }
    float gS1 = qs1[0];
#pragma unroll
    for (int qq = 1; qq < 4; qq++) if (qs1[qq] > gS1) gS1 = qs1[qq];

    const float eps = en2 * (1.0f / 8192.0f);   // 2^-13 * ||e||^2 (proven)
    const float thr = gS1 - eps;

    bool needfull = false;
#pragma unroll
    for (int qq = 0; qq < 4; qq++) needfull |= (qs2[qq] >= thr);

    if (needfull) {
        if (lane == 0) {
            int pos = atomicAdd(&g_fb_count, 1);
            g_fb_rows[pos] = row;
        }
        return;
    }

    // exact-rescore qualifying quarter winners (1..4 candidates)
    float bestsc = -1.f; int bestk = 0; float bestdot = 0.f;
#pragma unroll
    for (int qq = 0; qq < 4; qq++) {
        if (qs1[qq] >= thr) {
            int k = qi1[qq];
            float4 c0 = __ldg(&C4[(size_t)k * 64 + lane * 2]);
            float4 c1 = __ldg(&C4[(size_t)k * 64 + lane * 2 + 1]);
            float pp = ev0.x * c0.x + ev0.y * c0.y + ev0.z * c0.z + ev0.w * c0.w +
                       ev1.x * c1.x + ev1.y * c1.y + ev1.z * c1.z + ev1.w * c1.w;
            float dot = warp_allsum(pp);
            float sc = dot * dot * g_inv_norms[k];
            if (sc > bestsc || (sc == bestsc && k < bestk)) {
                bestsc = sc; bestk = k; bestdot = dot;
            }
        }
    }

    float alpha = bestdot * g_inv_norms[bestk];
    float4 cv0 = __ldg(&C4[(size_t)bestk * 64 + lane * 2]);
    float4 cv1 = __ldg(&C4[(size_t)bestk * 64 + lane * 2 + 1]);
    float4* Z4 = reinterpret_cast<float4*>(z_out);
    Z4[(size_t)row * 64 + lane * 2] =
        make_float4(alpha * cv0.x, alpha * cv0.y, alpha * cv0.z, alpha * cv0.w);
    Z4[(size_t)row * 64 + lane * 2 + 1] =
        make_float4(alpha * cv1.x, alpha * cv1.y, alpha * cv1.z, alpha * cv1.w);
    if (lane == 0 && write_idx) idx_out[row] = (float)bestk;
}

// ===========================================================================
// K5: exact fp32 rescan for fallback rows. 8 rows per CTA-group (grid-stride),
// 512 threads / 16 warps: warp w scans codes [64w, 64w+64), 2 codes per
// iteration with loads hoisted ahead of 16 parallel reduce chains.
// Critical path ~8x shorter than the 8-warp/128-code version.
// ===========================================================================
__global__ __launch_bounds__(512) void vq_fb_kernel(
    const float* __restrict__ E, const float* __restrict__ C,
    float* __restrict__ z_out, float* __restrict__ idx_out, int write_idx)
{
    __shared__ float se[8][256];
    __shared__ float ws[8][16];   // [row][warp]
    __shared__ int   wi[8][16];
    __shared__ int   s_rid[8];
    __shared__ int   s_kb[8];
    const int tid = threadIdx.x;
    const int warp = tid >> 5;    // 0..15
    const int lane = tid & 31;
    const float4* C4 = reinterpret_cast<const float4*>(C);

    const int nfb = g_fb_count;
    const int ngrp = (nfb + 7) >> 3;
    for (int g = blockIdx.x; g < ngrp; g += FB_CTAS) {
        const int r0 = g * 8;
        const int cnt = (nfb - r0 < 8) ? (nfb - r0) : 8;
        if (tid < 8) s_rid[tid] = (tid < cnt) ? g_fb_rows[r0 + tid] : -1;
        __syncthreads();
        for (int idx = tid; idx < 8 * 256; idx += 512) {
            int rr = idx >> 8;
            se[rr][idx & 255] = (s_rid[rr] >= 0) ? E[(size_t)s_rid[rr] * D_SZ + (idx & 255)] : 0.f;
        }
        __syncthreads();

        // stage all 8 rows into registers (lane owns dims [lane*8, lane*8+8))
        float4 ea[8], eb[8];
#pragma unroll
        for (int r = 0; r < 8; r++) {
            ea[r] = *reinterpret_cast<const float4*>(&se[r][lane * 8]);
            eb[r] = *reinterpret_cast<const float4*>(&se[r][lane * 8 + 4]);
        }

        float best[8]; int bi[8];
#pragma unroll
        for (int r = 0; r < 8; r++) { best[r] = -1.f; bi[r] = 0; }

        const int k0 = warp * 64;
        // prologue loads for first code pair
        float4 c0a = __ldg(&C4[(size_t)k0 * 64 + lane * 2]);
        float4 c1a = __ldg(&C4[(size_t)k0 * 64 + lane * 2 + 1]);
        float4 c0b = __ldg(&C4[(size_t)(k0 + 1) * 64 + lane * 2]);
        float4 c1b = __ldg(&C4[(size_t)(k0 + 1) * 64 + lane * 2 + 1]);
        for (int kk = 0; kk < 64; kk += 2) {
            const int k = k0 + kk;
            // partials for 8 rows x 2 codes = 16 independent chains
            float pp[16];
#pragma unroll
            for (int r = 0; r < 8; r++) {
                pp[r] = ea[r].x * c0a.x + ea[r].y * c0a.y + ea[r].z * c0a.z + ea[r].w * c0a.w +
                        eb[r].x * c1a.x + eb[r].y * c1a.y + eb[r].z * c1a.z + eb[r].w * c1a.w;
                pp[8 + r] = ea[r].x * c0b.x + ea[r].y * c0b.y + ea[r].z * c0b.z + ea[r].w * c0b.w +
                            eb[r].x * c1b.x + eb[r].y * c1b.y + eb[r].z * c1b.z + eb[r].w * c1b.w;
            }
            // prefetch next pair while reducing
            if (kk < 62) {
                c0a = __ldg(&C4[(size_t)(k + 2) * 64 + lane * 2]);
                c1a = __ldg(&C4[(size_t)(k + 2) * 64 + lane * 2 + 1]);
                c0b = __ldg(&C4[(size_t)(k + 3) * 64 + lane * 2]);
                c1b = __ldg(&C4[(size_t)(k + 3) * 64 + lane * 2 + 1]);
            }
#pragma unroll
            for (int o = 16; o > 0; o >>= 1)
#pragma unroll
                for (int u = 0; u < 16; u++)
                    pp[u] += __shfl_xor_sync(0xffffffffu, pp[u], o);
            const float in0 = g_inv_norms[k];
            const float in1 = g_inv_norms[k + 1];
#pragma unroll
            for (int r = 0; r < 8; r++) {
                float sc0 = pp[r] * pp[r] * in0;
                if (sc0 > best[r]) { best[r] = sc0; bi[r] = k; }          // ascending k
                float sc1 = pp[8 + r] * pp[8 + r] * in1;
                if (sc1 > best[r]) { best[r] = sc1; bi[r] = k + 1; }
            }
        }
        if (lane == 0) {
#pragma unroll
            for (int r = 0; r < 8; r++) { ws[r][warp] = best[r]; wi[r][warp] = bi[r]; }
        }
        __syncthreads();
        if (tid < 8) {   // merge row tid across warps (ascending warp = ascending k block)
            float bb = -1.f; int bk = 0;
#pragma unroll
            for (int w = 0; w < 16; w++)
                if (ws[tid][w] > bb) { bb = ws[tid][w]; bk = wi[tid][w]; }
            s_kb[tid] = bk;
        }
        __syncthreads();

        // warps 0..7 finalize rows 0..7: exact dot -> alpha -> z, idx
        if (warp < 8) {
            const int row = s_rid[warp];
            if (row >= 0) {
                const int kb = s_kb[warp];
                float4 c0 = __ldg(&C4[(size_t)kb * 64 + lane * 2]);
                float4 c1 = __ldg(&C4[(size_t)kb * 64 + lane * 2 + 1]);
                float pp = ea[warp].x * c0.x + ea[warp].y * c0.y + ea[warp].z * c0.z + ea[warp].w * c0.w +
                           eb[warp].x * c1.x + eb[warp].y * c1.y + eb[warp].z * c1.z + eb[warp].w * c1.w;
                float dot = warp_allsum(pp);
                float alpha = dot * g_inv_norms[kb];
                float4* Z4 = reinterpret_cast<float4*>(z_out);
                Z4[(size_t)row * 64 + lane * 2] =
                    make_float4(alpha * c0.x, alpha * c0.y, alpha * c0.z, alpha * c0.w);
                Z4[(size_t)row * 64 + lane * 2 + 1] =
                    make_float4(alpha * c1.x, alpha * c1.y, alpha * c1.z, alpha * c1.w);
                if (lane == 0 && write_idx) idx_out[row] = (float)kb;
            }
        }
        __syncthreads();
    }
}

// ===========================================================================
extern "C" void kernel_launch(void* const* d_in, const int* in_sizes, int n_in,
                              void* d_out, int out_size) {
    const float* E = (const float*)d_in[0];
    const float* C = (const float*)d_in[1];
    float* z = (float*)d_out;
    float* idx = z + (size_t)B_SZ * D_SZ;
    int write_idx = (out_size >= B_SZ * D_SZ + B_SZ) ? 1 : 0;

    cudaFuncSetAttribute(vq_gemm_kernel,
                         cudaFuncAttributeMaxDynamicSharedMemorySize, SMEM_K3);

    vq_prep_kernel<<<K_SZ, 64>>>(C);
    vq_gemm_kernel<<<(B_SZ / 128) * 4, NTHREADS, SMEM_K3>>>(E);
    vq_final_kernel<<<B_SZ / 8, 256>>>(E, C, z, idx, write_idx);
    vq_fb_kernel<<<FB_CTAS, 512>>>(E, C, z, idx, write_idx);
}